// round 16
// baseline (speedup 1.0000x reference)
#include <cuda_runtime.h>
#include <cuda_bf16.h>

#define NTOK 50
#define BTOK 3200
#define P    72                 // plane pitch in bf16 elems (144B rows; LDSM conflict-free)
#define PB   (P*2)              // 144 B
#define PLANE_E (64*P)
#define PLANE_B (64*PB)         // 9216 B

// 6 dedicated planes: Fh Fl Gh Gl Hh Hl
#define OFF_FH 0
#define OFF_FL (1*PLANE_B)
#define OFF_GH (2*PLANE_B)
#define OFF_GL (3*PLANE_B)
#define OFF_HH (4*PLANE_B)
#define OFF_HL (5*PLANE_B)
#define SMEM_BYTES (6*PLANE_B)  // 55,296 B -> 4 CTAs/SM

// weight B-fragments in register layout: [Kh 16][Kl 16][Q 16] sets x 32 lanes x uint4
__device__ __align__(16) uint4 gFrag[48 * 32];

__device__ __forceinline__ void ldsm_x4(unsigned* r, unsigned a) {
    asm volatile("ldmatrix.sync.aligned.m8n8.x4.shared.b16 {%0,%1,%2,%3}, [%4];"
                 : "=r"(r[0]), "=r"(r[1]), "=r"(r[2]), "=r"(r[3]) : "r"(a));
}
__device__ __forceinline__ void ldsm_x4t(unsigned* r, unsigned a) {
    asm volatile("ldmatrix.sync.aligned.m8n8.x4.trans.shared.b16 {%0,%1,%2,%3}, [%4];"
                 : "=r"(r[0]), "=r"(r[1]), "=r"(r[2]), "=r"(r[3]) : "r"(a));
}
__device__ __forceinline__ void mma16(float* d, const unsigned* a, const unsigned* b) {
    asm volatile(
        "mma.sync.aligned.m16n8k16.row.col.f32.bf16.bf16.f32 "
        "{%0,%1,%2,%3}, {%4,%5,%6,%7}, {%8,%9}, {%0,%1,%2,%3};\n"
        : "+f"(d[0]), "+f"(d[1]), "+f"(d[2]), "+f"(d[3])
        : "r"(a[0]), "r"(a[1]), "r"(a[2]), "r"(a[3]), "r"(b[0]), "r"(b[1]));
}
__device__ __forceinline__ void bsplit(float x, __nv_bfloat16& h, __nv_bfloat16& l) {
    h = __float2bfloat16_rn(x);
    l = __float2bfloat16_rn(x - __bfloat162float(h));
}

// ---- prep: split weights, REPLAY the exact ldsm loads, store fragments.
//      1024 threads: split loop = 2 iters, replay <= 2 sets/warp. ----
__global__ __launch_bounds__(1024)
void SAM3E_prep(const float* __restrict__ Kw, const float* __restrict__ Qw)
{
    __shared__ __nv_bfloat16 sw[3 * PLANE_E];        // Kh, Kl, Qh planes
    const int tid = threadIdx.x;
    const float2* K2 = (const float2*)Kw;
    const float2* Q2 = (const float2*)Qw;
    for (int i = tid; i < 2048; i += 1024) {
        int r = i >> 5, c = (i & 31) << 1;
        __nv_bfloat16 hx, lx, hy, ly;
        float2 v = K2[i];
        bsplit(v.x, hx, lx); bsplit(v.y, hy, ly);
        *(__nv_bfloat162*)&sw[0 * PLANE_E + r * P + c] = __halves2bfloat162(hx, hy);
        *(__nv_bfloat162*)&sw[1 * PLANE_E + r * P + c] = __halves2bfloat162(lx, ly);
        float2 u = Q2[i];
        *(__nv_bfloat162*)&sw[2 * PLANE_E + r * P + c] =
            __halves2bfloat162(__float2bfloat16_rn(u.x), __float2bfloat16_rn(u.y));
    }
    __syncthreads();
    const unsigned sbase = (unsigned)__cvta_generic_to_shared(sw);
    const int w = tid >> 5, lane = tid & 31;
    const int q = lane & 7, b8 = (lane >> 3) & 1, b16 = (lane >> 4) & 1;
    for (int s = w; s < 48; s += 32) {
        const int kind = s >> 4;          // 0 Kh, 1 Kl, 2 Qh
        const int kk = (s >> 2) & 3, ct = s & 3;
        unsigned r[4];
        if (kind < 2) {                   // trans read, exactly main's old K path
            unsigned a = sbase + kind * PLANE_B
                       + 2u * ((kk * 16 + 8 * b8 + q) * P + ct * 16 + 8 * b16);
            ldsm_x4t(r, a);
        } else {                          // non-trans read, exactly main's old Q path
            unsigned a = sbase + 2 * PLANE_B
                       + 2u * ((ct * 16 + q + 8 * b16) * P + kk * 16 + 8 * b8);
            ldsm_x4(r, a);
        }
        gFrag[s * 32 + lane] = make_uint4(r[0], r[1], r[2], r[3]);
    }
}

__global__ __launch_bounds__(256, 4)
void SAM3E_kernel(const float* __restrict__ Fg,
                  float* __restrict__ outg)
{
    extern __shared__ __nv_bfloat16 sb[];
    const unsigned sbase = (unsigned)__cvta_generic_to_shared(sb);
    __nv_bfloat16* sFh = sb;
    __nv_bfloat16* sFl = sb + 1 * PLANE_E;
    __nv_bfloat16* sGh = sb + 2 * PLANE_E;
    __nv_bfloat16* sGl = sb + 3 * PLANE_E;
    __nv_bfloat16* sHh = sb + 4 * PLANE_E;
    __nv_bfloat16* sHl = sb + 5 * PLANE_E;

    const int b   = blockIdx.x;
    const int tid = threadIdx.x;

    // ---- stage F (float4 loads, split, packed uint2 stores) ----
    const float4* F4 = (const float4*)(Fg + (size_t)b * BTOK);
    for (int i = tid; i < 800; i += 256) {
        float4 v = F4[i];
        int n = i >> 4, d = (i & 15) << 2;
        __nv_bfloat16 h0,l0,h1,l1,h2,l2,h3,l3;
        bsplit(v.x, h0, l0); bsplit(v.y, h1, l1);
        bsplit(v.z, h2, l2); bsplit(v.w, h3, l3);
        __nv_bfloat162 ph0 = __halves2bfloat162(h0, h1), ph1 = __halves2bfloat162(h2, h3);
        __nv_bfloat162 pl0 = __halves2bfloat162(l0, l1), pl1 = __halves2bfloat162(l2, l3);
        uint2 uh, ul;
        uh.x = *(unsigned*)&ph0; uh.y = *(unsigned*)&ph1;
        ul.x = *(unsigned*)&pl0; ul.y = *(unsigned*)&pl1;
        *(uint2*)&sFh[n * P + d] = uh;
        *(uint2*)&sFl[n * P + d] = ul;
    }
    for (int i = tid; i < 14 * (P / 2); i += 256) {     // zero-pad rows 50..63
        int off = 50 * P + 2 * i;
        *(unsigned*)&sFh[off] = 0u;
        *(unsigned*)&sFl[off] = 0u;
    }
    __syncthreads();

    const int lane = tid & 31, w = tid >> 5;
    const int m0 = (w >> 1) * 16;           // 16-row band (A2/B/epilogue)
    const int n0 = (w & 1) * 32;            // 32-col half
    const int q   = lane & 7;
    const int b8  = (lane >> 3) & 1;
    const int b16 = (lane >> 4) & 1;
    const int g   = lane >> 2, t4 = lane & 3;

    const uint4* __restrict__ fKh = gFrag;
    const uint4* __restrict__ fKl = gFrag + 16 * 32;
    const uint4* __restrict__ fQ  = gFrag + 32 * 32;

    // ========== Phase A2: H = F @ K_w (3-term), QF = F @ Q_w^T (1-term) ==========
    float accH[4][4] = {};
    float accQ[4][4] = {};
    {
        const unsigned a2 = sbase + OFF_FH + 2u * ((m0 + 8 * b8 + q) * P + 8 * b16);
        #pragma unroll
        for (int kk = 0; kk < 4; ++kk) {
            unsigned ah[4], al[4];
            ldsm_x4(ah, a2 + kk * 32);
            ldsm_x4(al, a2 + kk * 32 + PLANE_B);
            #pragma unroll
            for (int p = 0; p < 2; ++p) {
                const int fi = (kk * 4 + (n0 >> 4) + p) * 32 + lane;
                uint4 bhv = fKh[fi], blv = fKl[fi], bqv = fQ[fi];
                const unsigned* bh = (const unsigned*)&bhv;
                const unsigned* bl = (const unsigned*)&blv;
                const unsigned* bq = (const unsigned*)&bqv;
                mma16(accH[2*p  ], ah, bh    );
                mma16(accH[2*p  ], al, bh    );
                mma16(accH[2*p  ], ah, bl    );
                mma16(accH[2*p+1], ah, bh + 2);
                mma16(accH[2*p+1], al, bh + 2);
                mma16(accH[2*p+1], ah, bl + 2);
                mma16(accQ[2*p  ], ah, bq    );
                mma16(accQ[2*p+1], ah, bq + 2);
            }
        }
    }

    // store H (split) into dedicated planes — no barrier needed (fresh planes)
    #pragma unroll
    for (int t = 0; t < 4; ++t) {
        const int col = n0 + 8 * t + 2 * t4;
        __nv_bfloat16 h0,l0,h1,l1,h2,l2,h3,l3;
        bsplit(accH[t][0],h0,l0); bsplit(accH[t][1],h1,l1);
        bsplit(accH[t][2],h2,l2); bsplit(accH[t][3],h3,l3);
        *(__nv_bfloat162*)&sHh[(m0 + g    ) * P + col] = __halves2bfloat162(h0, h1);
        *(__nv_bfloat162*)&sHl[(m0 + g    ) * P + col] = __halves2bfloat162(l0, l1);
        *(__nv_bfloat162*)&sHh[(m0 + g + 8) * P + col] = __halves2bfloat162(h2, h3);
        *(__nv_bfloat162*)&sHl[(m0 + g + 8) * P + col] = __halves2bfloat162(l2, l3);
    }

    // ========== Phase A1: G = F^T F — symmetric, 6 of 8 tiles, NO mirror ==========
    if (w < 6) {
        const int gm0 = 16 * (w < 4 ? w : w - 2);
        const int gn0 = (w < 4) ? 0 : 32;
        float accG[4][4] = {};
        const unsigned a1 = sbase + OFF_FH + 2u * ((8 * b16 + q) * P + gm0 + 8 * b8);
        const unsigned b1 = sbase + OFF_FH + 2u * ((8 * b8 + q) * P + gn0 + 8 * b16);
        #pragma unroll
        for (int kk = 0; kk < 4; ++kk) {
            unsigned ah[4], al[4];
            ldsm_x4t(ah, a1 + kk * 16 * PB);
            ldsm_x4t(al, a1 + kk * 16 * PB + PLANE_B);
            #pragma unroll
            for (int p = 0; p < 2; ++p) {
                unsigned bh[4], bl[4];
                ldsm_x4t(bh, b1 + kk * 16 * PB + p * 32);
                ldsm_x4t(bl, b1 + kk * 16 * PB + p * 32 + PLANE_B);
                mma16(accG[2*p  ], ah, bh    );
                mma16(accG[2*p  ], al, bh    );
                mma16(accG[2*p  ], ah, bl    );
                mma16(accG[2*p+1], ah, bh + 2);
                mma16(accG[2*p+1], al, bh + 2);
                mma16(accG[2*p+1], ah, bl + 2);
            }
        }
        #pragma unroll
        for (int t = 0; t < 4; ++t) {
            const int col = gn0 + 8 * t + 2 * t4;
            __nv_bfloat16 h0,l0,h1,l1,h2,l2,h3,l3;
            bsplit(accG[t][0],h0,l0); bsplit(accG[t][1],h1,l1);
            bsplit(accG[t][2],h2,l2); bsplit(accG[t][3],h3,l3);
            const int r1 = gm0 + g, r2 = gm0 + g + 8;
            *(__nv_bfloat162*)&sGh[r1 * P + col] = __halves2bfloat162(h0, h1);
            *(__nv_bfloat162*)&sGl[r1 * P + col] = __halves2bfloat162(l0, l1);
            *(__nv_bfloat162*)&sGh[r2 * P + col] = __halves2bfloat162(h2, h3);
            *(__nv_bfloat162*)&sGl[r2 * P + col] = __halves2bfloat162(l2, l3);
        }
    }
    __syncthreads();   // single barrier: G + H stores visible to all warps

    // ========== Phase B: T = H @ G ==========
    // n0=0 warps, kk>=2: G[0:32,32:64] is absent -> trans-read G[32:64,0:32] (symmetry).
    float accT[4][4] = {};
    {
        const unsigned a3  = sbase + OFF_HH + 2u * ((m0 + 8 * b8 + q) * P + 8 * b16);
        const unsigned b3n = sbase + OFF_GH + 2u * ((n0 + q + 8 * b16) * P + 8 * b8);
        const unsigned b3t = sbase + OFF_GH + 2u * ((32 + 8 * b8 + q) * P + 8 * b16);
        #pragma unroll
        for (int kk = 0; kk < 4; ++kk) {
            unsigned ah[4], al[4];
            ldsm_x4(ah, a3 + kk * 32);
            ldsm_x4(al, a3 + kk * 32 + PLANE_B);
            #pragma unroll
            for (int p = 0; p < 2; ++p) {
                unsigned bh[4], bl[4];
                if (n0 == 0 && kk >= 2) {
                    ldsm_x4t(bh, b3t + (kk - 2) * 16 * PB + p * 32);
                    ldsm_x4t(bl, b3t + (kk - 2) * 16 * PB + p * 32 + PLANE_B);
                } else {
                    ldsm_x4(bh, b3n + kk * 32 + p * 16 * PB);
                    ldsm_x4(bl, b3n + kk * 32 + p * 16 * PB + PLANE_B);
                }
                mma16(accT[2*p  ], ah, bh    );
                mma16(accT[2*p  ], al, bh    );
                mma16(accT[2*p  ], ah, bl    );
                mma16(accT[2*p+1], ah, bh + 2);
                mma16(accT[2*p+1], al, bh + 2);
                mma16(accT[2*p+1], ah, bl + 2);
            }
        }
    }

    // ========== Epilogue: out = F .* T + QF  (rows < 50) ==========
    float* ob = outg + (size_t)b * BTOK;
    const int r1 = m0 + g;
    const int r2 = m0 + g + 8;
    #pragma unroll
    for (int t = 0; t < 4; ++t) {
        const int col = n0 + 8 * t + 2 * t4;
        if (r1 < NTOK) {
            float2 fh = __bfloat1622float2(*(__nv_bfloat162*)&sFh[r1 * P + col]);
            float2 fl = __bfloat1622float2(*(__nv_bfloat162*)&sFl[r1 * P + col]);
            float2 o;
            o.x = (fh.x + fl.x) * accT[t][0] + accQ[t][0];
            o.y = (fh.y + fl.y) * accT[t][1] + accQ[t][1];
            *(float2*)&ob[r1 * 64 + col] = o;
        }
        if (r2 < NTOK) {
            float2 fh = __bfloat1622float2(*(__nv_bfloat162*)&sFh[r2 * P + col]);
            float2 fl = __bfloat1622float2(*(__nv_bfloat162*)&sFl[r2 * P + col]);
            float2 o;
            o.x = (fh.x + fl.x) * accT[t][2] + accQ[t][2];
            o.y = (fh.y + fl.y) * accT[t][3] + accQ[t][3];
            *(float2*)&ob[r2 * 64 + col] = o;
        }
    }
}

extern "C" void kernel_launch(void* const* d_in, const int* in_sizes, int n_in,
                              void* d_out, int out_size)
{
    const float* F  = (const float*)d_in[0];
    const float* Kw = (const float*)d_in[1];
    const float* Qw = (const float*)d_in[2];
    float* out      = (float*)d_out;

    const int B = in_sizes[0] / BTOK;                   // 8192

    cudaFuncSetAttribute(SAM3E_kernel,
                         cudaFuncAttributeMaxDynamicSharedMemorySize, SMEM_BYTES);

    SAM3E_prep<<<1, 1024>>>(Kw, Qw);
    SAM3E_kernel<<<B, 256, SMEM_BYTES>>>(F, out);
}

// round 17
// speedup vs baseline: 1.4412x; 1.4412x over previous
#include <cuda_runtime.h>
#include <cuda_bf16.h>

#define NTOK 50
#define BTOK 3200
#define P    72                 // plane pitch in bf16 elems (144B rows; LDSM conflict-free)
#define PB   (P*2)              // 144 B
#define PLANE_E (64*P)
#define PLANE_B (64*PB)         // 9216 B

// 6 dedicated planes: Fh Fl Gh Gl Hh Hl
#define OFF_FH 0
#define OFF_FL (1*PLANE_B)
#define OFF_GH (2*PLANE_B)
#define OFF_GL (3*PLANE_B)
#define OFF_HH (4*PLANE_B)
#define OFF_HL (5*PLANE_B)
#define SMEM_BYTES (6*PLANE_B)  // 55,296 B -> 4 CTAs/SM

// weight B-fragments in register layout: [Kh 16][Kl 16][Q 16] sets x 32 lanes x uint4
__device__ __align__(16) uint4 gFrag[48 * 32];

__device__ __forceinline__ void ldsm_x4(unsigned* r, unsigned a) {
    asm volatile("ldmatrix.sync.aligned.m8n8.x4.shared.b16 {%0,%1,%2,%3}, [%4];"
                 : "=r"(r[0]), "=r"(r[1]), "=r"(r[2]), "=r"(r[3]) : "r"(a));
}
__device__ __forceinline__ void ldsm_x4t(unsigned* r, unsigned a) {
    asm volatile("ldmatrix.sync.aligned.m8n8.x4.trans.shared.b16 {%0,%1,%2,%3}, [%4];"
                 : "=r"(r[0]), "=r"(r[1]), "=r"(r[2]), "=r"(r[3]) : "r"(a));
}
__device__ __forceinline__ void mma16(float* d, const unsigned* a, const unsigned* b) {
    asm volatile(
        "mma.sync.aligned.m16n8k16.row.col.f32.bf16.bf16.f32 "
        "{%0,%1,%2,%3}, {%4,%5,%6,%7}, {%8,%9}, {%0,%1,%2,%3};\n"
        : "+f"(d[0]), "+f"(d[1]), "+f"(d[2]), "+f"(d[3])
        : "r"(a[0]), "r"(a[1]), "r"(a[2]), "r"(a[3]), "r"(b[0]), "r"(b[1]));
}
__device__ __forceinline__ void bsplit(float x, __nv_bfloat16& h, __nv_bfloat16& l) {
    h = __float2bfloat16_rn(x);
    l = __float2bfloat16_rn(x - __bfloat162float(h));
}

// ---- prep: 6 blocks x 256 thr. Each block stages the weight planes (redundant,
//      parallel) and its 8 warps replay 8 of the 48 fragment sets (no loop). ----
__global__ __launch_bounds__(256)
void SAM3E_prep(const float* __restrict__ Kw, const float* __restrict__ Qw)
{
    __shared__ __nv_bfloat16 sw[3 * PLANE_E];        // Kh, Kl, Qh planes
    const int tid = threadIdx.x;
    const float2* K2 = (const float2*)Kw;
    const float2* Q2 = (const float2*)Qw;
    for (int i = tid; i < 2048; i += 256) {
        int r = i >> 5, c = (i & 31) << 1;
        __nv_bfloat16 hx, lx, hy, ly;
        float2 v = K2[i];
        bsplit(v.x, hx, lx); bsplit(v.y, hy, ly);
        *(__nv_bfloat162*)&sw[0 * PLANE_E + r * P + c] = __halves2bfloat162(hx, hy);
        *(__nv_bfloat162*)&sw[1 * PLANE_E + r * P + c] = __halves2bfloat162(lx, ly);
        float2 u = Q2[i];
        *(__nv_bfloat162*)&sw[2 * PLANE_E + r * P + c] =
            __halves2bfloat162(__float2bfloat16_rn(u.x), __float2bfloat16_rn(u.y));
    }
    __syncthreads();
    const unsigned sbase = (unsigned)__cvta_generic_to_shared(sw);
    const int w = tid >> 5, lane = tid & 31;
    const int q = lane & 7, b8 = (lane >> 3) & 1, b16 = (lane >> 4) & 1;
    const int s = blockIdx.x * 8 + w;               // 0..47, one set per warp
    const int kind = s >> 4;                        // 0 Kh, 1 Kl, 2 Qh
    const int kk = (s >> 2) & 3, ct = s & 3;
    unsigned r[4];
    if (kind < 2) {                                 // trans read, exactly main's old K path
        unsigned a = sbase + kind * PLANE_B
                   + 2u * ((kk * 16 + 8 * b8 + q) * P + ct * 16 + 8 * b16);
        ldsm_x4t(r, a);
    } else {                                        // non-trans read, exactly main's old Q path
        unsigned a = sbase + 2 * PLANE_B
                   + 2u * ((ct * 16 + q + 8 * b16) * P + kk * 16 + 8 * b8);
        ldsm_x4(r, a);
    }
    gFrag[s * 32 + lane] = make_uint4(r[0], r[1], r[2], r[3]);
}

__global__ __launch_bounds__(256, 4)
void SAM3E_kernel(const float* __restrict__ Fg,
                  float* __restrict__ outg)
{
    extern __shared__ __nv_bfloat16 sb[];
    const unsigned sbase = (unsigned)__cvta_generic_to_shared(sb);
    __nv_bfloat16* sFh = sb;
    __nv_bfloat16* sFl = sb + 1 * PLANE_E;
    __nv_bfloat16* sGh = sb + 2 * PLANE_E;
    __nv_bfloat16* sGl = sb + 3 * PLANE_E;
    __nv_bfloat16* sHh = sb + 4 * PLANE_E;
    __nv_bfloat16* sHl = sb + 5 * PLANE_E;

    const int b   = blockIdx.x;
    const int tid = threadIdx.x;

    // ---- stage F (float4 loads, split, packed uint2 stores) ----
    const float4* F4 = (const float4*)(Fg + (size_t)b * BTOK);
    for (int i = tid; i < 800; i += 256) {
        float4 v = F4[i];
        int n = i >> 4, d = (i & 15) << 2;
        __nv_bfloat16 h0,l0,h1,l1,h2,l2,h3,l3;
        bsplit(v.x, h0, l0); bsplit(v.y, h1, l1);
        bsplit(v.z, h2, l2); bsplit(v.w, h3, l3);
        __nv_bfloat162 ph0 = __halves2bfloat162(h0, h1), ph1 = __halves2bfloat162(h2, h3);
        __nv_bfloat162 pl0 = __halves2bfloat162(l0, l1), pl1 = __halves2bfloat162(l2, l3);
        uint2 uh, ul;
        uh.x = *(unsigned*)&ph0; uh.y = *(unsigned*)&ph1;
        ul.x = *(unsigned*)&pl0; ul.y = *(unsigned*)&pl1;
        *(uint2*)&sFh[n * P + d] = uh;
        *(uint2*)&sFl[n * P + d] = ul;
    }
    for (int i = tid; i < 14 * (P / 2); i += 256) {     // zero-pad rows 50..63
        int off = 50 * P + 2 * i;
        *(unsigned*)&sFh[off] = 0u;
        *(unsigned*)&sFl[off] = 0u;
    }
    __syncthreads();

    const int lane = tid & 31, w = tid >> 5;
    const int m0 = (w >> 1) * 16;           // 16-row band (A2/B/epilogue)
    const int n0 = (w & 1) * 32;            // 32-col half
    const int q   = lane & 7;
    const int b8  = (lane >> 3) & 1;
    const int b16 = (lane >> 4) & 1;
    const int g   = lane >> 2, t4 = lane & 3;

    const uint4* __restrict__ fKh = gFrag;
    const uint4* __restrict__ fKl = gFrag + 16 * 32;
    const uint4* __restrict__ fQ  = gFrag + 32 * 32;

    // ========== Phase A2: H = F @ K_w (3-term), QF = F @ Q_w^T (1-term) ==========
    float accH[4][4] = {};
    float accQ[4][4] = {};
    {
        const unsigned a2 = sbase + OFF_FH + 2u * ((m0 + 8 * b8 + q) * P + 8 * b16);
        #pragma unroll
        for (int kk = 0; kk < 4; ++kk) {
            unsigned ah[4], al[4];
            ldsm_x4(ah, a2 + kk * 32);
            ldsm_x4(al, a2 + kk * 32 + PLANE_B);
            #pragma unroll
            for (int p = 0; p < 2; ++p) {
                const int fi = (kk * 4 + (n0 >> 4) + p) * 32 + lane;
                uint4 bhv = fKh[fi], blv = fKl[fi], bqv = fQ[fi];
                const unsigned* bh = (const unsigned*)&bhv;
                const unsigned* bl = (const unsigned*)&blv;
                const unsigned* bq = (const unsigned*)&bqv;
                mma16(accH[2*p  ], ah, bh    );
                mma16(accH[2*p  ], al, bh    );
                mma16(accH[2*p  ], ah, bl    );
                mma16(accH[2*p+1], ah, bh + 2);
                mma16(accH[2*p+1], al, bh + 2);
                mma16(accH[2*p+1], ah, bl + 2);
                mma16(accQ[2*p  ], ah, bq    );
                mma16(accQ[2*p+1], ah, bq + 2);
            }
        }
    }

    // store H (split) into dedicated planes — no barrier needed (fresh planes)
    #pragma unroll
    for (int t = 0; t < 4; ++t) {
        const int col = n0 + 8 * t + 2 * t4;
        __nv_bfloat16 h0,l0,h1,l1,h2,l2,h3,l3;
        bsplit(accH[t][0],h0,l0); bsplit(accH[t][1],h1,l1);
        bsplit(accH[t][2],h2,l2); bsplit(accH[t][3],h3,l3);
        *(__nv_bfloat162*)&sHh[(m0 + g    ) * P + col] = __halves2bfloat162(h0, h1);
        *(__nv_bfloat162*)&sHl[(m0 + g    ) * P + col] = __halves2bfloat162(l0, l1);
        *(__nv_bfloat162*)&sHh[(m0 + g + 8) * P + col] = __halves2bfloat162(h2, h3);
        *(__nv_bfloat162*)&sHl[(m0 + g + 8) * P + col] = __halves2bfloat162(l2, l3);
    }

    // ========== Phase A1: G = F^T F — symmetric, 6 of 8 tiles, NO mirror ==========
    if (w < 6) {
        const int gm0 = 16 * (w < 4 ? w : w - 2);
        const int gn0 = (w < 4) ? 0 : 32;
        float accG[4][4] = {};
        const unsigned a1 = sbase + OFF_FH + 2u * ((8 * b16 + q) * P + gm0 + 8 * b8);
        const unsigned b1 = sbase + OFF_FH + 2u * ((8 * b8 + q) * P + gn0 + 8 * b16);
        #pragma unroll
        for (int kk = 0; kk < 4; ++kk) {
            unsigned ah[4], al[4];
            ldsm_x4t(ah, a1 + kk * 16 * PB);
            ldsm_x4t(al, a1 + kk * 16 * PB + PLANE_B);
            #pragma unroll
            for (int p = 0; p < 2; ++p) {
                unsigned bh[4], bl[4];
                ldsm_x4t(bh, b1 + kk * 16 * PB + p * 32);
                ldsm_x4t(bl, b1 + kk * 16 * PB + p * 32 + PLANE_B);
                mma16(accG[2*p  ], ah, bh    );
                mma16(accG[2*p  ], al, bh    );
                mma16(accG[2*p  ], ah, bl    );
                mma16(accG[2*p+1], ah, bh + 2);
                mma16(accG[2*p+1], al, bh + 2);
                mma16(accG[2*p+1], ah, bl + 2);
            }
        }
        #pragma unroll
        for (int t = 0; t < 4; ++t) {
            const int col = gn0 + 8 * t + 2 * t4;
            __nv_bfloat16 h0,l0,h1,l1,h2,l2,h3,l3;
            bsplit(accG[t][0],h0,l0); bsplit(accG[t][1],h1,l1);
            bsplit(accG[t][2],h2,l2); bsplit(accG[t][3],h3,l3);
            const int r1 = gm0 + g, r2 = gm0 + g + 8;
            *(__nv_bfloat162*)&sGh[r1 * P + col] = __halves2bfloat162(h0, h1);
            *(__nv_bfloat162*)&sGl[r1 * P + col] = __halves2bfloat162(l0, l1);
            *(__nv_bfloat162*)&sGh[r2 * P + col] = __halves2bfloat162(h2, h3);
            *(__nv_bfloat162*)&sGl[r2 * P + col] = __halves2bfloat162(l2, l3);
        }
    }
    __syncthreads();   // single barrier: G + H stores visible to all warps

    // ========== Phase B: T = H @ G ==========
    // n0=0 warps, kk>=2: G[0:32,32:64] is absent -> trans-read G[32:64,0:32] (symmetry).
    float accT[4][4] = {};
    {
        const unsigned a3  = sbase + OFF_HH + 2u * ((m0 + 8 * b8 + q) * P + 8 * b16);
        const unsigned b3n = sbase + OFF_GH + 2u * ((n0 + q + 8 * b16) * P + 8 * b8);
        const unsigned b3t = sbase + OFF_GH + 2u * ((32 + 8 * b8 + q) * P + 8 * b16);
        #pragma unroll
        for (int kk = 0; kk < 4; ++kk) {
            unsigned ah[4], al[4];
            ldsm_x4(ah, a3 + kk * 32);
            ldsm_x4(al, a3 + kk * 32 + PLANE_B);
            #pragma unroll
            for (int p = 0; p < 2; ++p) {
                unsigned bh[4], bl[4];
                if (n0 == 0 && kk >= 2) {
                    ldsm_x4t(bh, b3t + (kk - 2) * 16 * PB + p * 32);
                    ldsm_x4t(bl, b3t + (kk - 2) * 16 * PB + p * 32 + PLANE_B);
                } else {
                    ldsm_x4(bh, b3n + kk * 32 + p * 16 * PB);
                    ldsm_x4(bl, b3n + kk * 32 + p * 16 * PB + PLANE_B);
                }
                mma16(accT[2*p  ], ah, bh    );
                mma16(accT[2*p  ], al, bh    );
                mma16(accT[2*p  ], ah, bl    );
                mma16(accT[2*p+1], ah, bh + 2);
                mma16(accT[2*p+1], al, bh + 2);
                mma16(accT[2*p+1], ah, bl + 2);
            }
        }
    }

    // ========== Epilogue: out = F .* T + QF  (rows < 50) ==========
    float* ob = outg + (size_t)b * BTOK;
    const int r1 = m0 + g;
    const int r2 = m0 + g + 8;
    #pragma unroll
    for (int t = 0; t < 4; ++t) {
        const int col = n0 + 8 * t + 2 * t4;
        if (r1 < NTOK) {
            float2 fh = __bfloat1622float2(*(__nv_bfloat162*)&sFh[r1 * P + col]);
            float2 fl = __bfloat1622float2(*(__nv_bfloat162*)&sFl[r1 * P + col]);
            float2 o;
            o.x = (fh.x + fl.x) * accT[t][0] + accQ[t][0];
            o.y = (fh.y + fl.y) * accT[t][1] + accQ[t][1];
            *(float2*)&ob[r1 * 64 + col] = o;
        }
        if (r2 < NTOK) {
            float2 fh = __bfloat1622float2(*(__nv_bfloat162*)&sFh[r2 * P + col]);
            float2 fl = __bfloat1622float2(*(__nv_bfloat162*)&sFl[r2 * P + col]);
            float2 o;
            o.x = (fh.x + fl.x) * accT[t][2] + accQ[t][2];
            o.y = (fh.y + fl.y) * accT[t][3] + accQ[t][3];
            *(float2*)&ob[r2 * 64 + col] = o;
        }
    }
}

extern "C" void kernel_launch(void* const* d_in, const int* in_sizes, int n_in,
                              void* d_out, int out_size)
{
    const float* F  = (const float*)d_in[0];
    const float* Kw = (const float*)d_in[1];
    const float* Qw = (const float*)d_in[2];
    float* out      = (float*)d_out;

    const int B = in_sizes[0] / BTOK;                   // 8192

    cudaFuncSetAttribute(SAM3E_kernel,
                         cudaFuncAttributeMaxDynamicSharedMemorySize, SMEM_BYTES);

    SAM3E_prep<<<6, 256>>>(Kw, Qw);
    SAM3E_kernel<<<B, 256, SMEM_BYTES>>>(F, out);
}